// round 1
// baseline (speedup 1.0000x reference)
#include <cuda_runtime.h>

#define NNODES 100000
#define NP     100352            // padded to 1024*98, multiple of 128
#define H      128
#define EMAX   1600000

// ---------------- device scratch (no allocation allowed) ----------------
__device__ float g_X[4][(size_t)NP * H];     // X0=emb(copy), X1..X3 layer outputs
__device__ float g_agg[(size_t)NP * H];
__device__ int   g_deg[NP];
__device__ float g_invdeg[NP];
__device__ int   g_rowstart[NP + 1];
__device__ int   g_cursor[NP];
__device__ int   g_csrsrc[EMAX];

// ---------------- CSR build ----------------
__global__ void k_zero_deg() {
    int i = blockIdx.x * blockDim.x + threadIdx.x;
    if (i < NP) g_deg[i] = 0;
}

__global__ void k_hist(const int* __restrict__ dst, int E) {
    int i = blockIdx.x * blockDim.x + threadIdx.x;
    if (i < E) atomicAdd(&g_deg[dst[i]], 1);
}

// single-block exclusive scan over NP (NP % 1024 == 0); also inv_deg + cursor=0
__global__ void k_scan() {
    __shared__ int warp_tot[32];
    int t = threadIdx.x;
    int lane = t & 31, wid = t >> 5;
    int running = 0;
    for (int base = 0; base < NP; base += 1024) {
        int v = g_deg[base + t];
        int x = v;
        #pragma unroll
        for (int d = 1; d < 32; d <<= 1) {
            int y = __shfl_up_sync(0xffffffffu, x, d);
            if (lane >= d) x += y;
        }
        if (lane == 31) warp_tot[wid] = x;
        __syncthreads();
        if (wid == 0) {
            int y = warp_tot[lane];
            #pragma unroll
            for (int d = 1; d < 32; d <<= 1) {
                int z = __shfl_up_sync(0xffffffffu, y, d);
                if (lane >= d) y += z;
            }
            warp_tot[lane] = y;
        }
        __syncthreads();
        int warp_off = (wid == 0) ? 0 : warp_tot[wid - 1];
        g_rowstart[base + t] = running + warp_off + x - v;
        int block_tot = warp_tot[31];
        __syncthreads();               // protect warp_tot for next iter
        running += block_tot;
        g_invdeg[base + t] = 1.0f / fmaxf((float)v, 1.0f);
        g_cursor[base + t] = 0;
    }
    if (t == 0) g_rowstart[NP] = running;
}

__global__ void k_fill(const int* __restrict__ src, const int* __restrict__ dst, int E) {
    int i = blockIdx.x * blockDim.x + threadIdx.x;
    if (i < E) {
        int d = dst[i];
        int p = atomicAdd(&g_cursor[d], 1);
        g_csrsrc[g_rowstart[d] + p] = src[i];
    }
}

__global__ void k_copy_emb(const float4* __restrict__ emb) {
    int i = blockIdx.x * blockDim.x + threadIdx.x;   // over NP*32 float4
    float4 v = make_float4(0.f, 0.f, 0.f, 0.f);
    if (i < NNODES * (H / 4)) v = emb[i];
    ((float4*)g_X[0])[i] = v;
}

// ---------------- aggregation: one warp per node, CSR gather ----------------
__global__ void k_agg(int layer) {
    int w = (blockIdx.x * blockDim.x + threadIdx.x) >> 5;
    if (w >= NP) return;
    int lane = threadIdx.x & 31;
    const float* __restrict__ xin = g_X[layer];
    int s0 = g_rowstart[w], s1 = g_rowstart[w + 1];
    float ax = 0.f, ay = 0.f, az = 0.f, aw = 0.f;
    int j = s0;
    for (; j + 4 <= s1; j += 4) {
        int i0 = g_csrsrc[j], i1 = g_csrsrc[j + 1], i2 = g_csrsrc[j + 2], i3 = g_csrsrc[j + 3];
        float4 a = ((const float4*)(xin + (size_t)i0 * H))[lane];
        float4 b = ((const float4*)(xin + (size_t)i1 * H))[lane];
        float4 c = ((const float4*)(xin + (size_t)i2 * H))[lane];
        float4 d = ((const float4*)(xin + (size_t)i3 * H))[lane];
        ax += (a.x + b.x) + (c.x + d.x);
        ay += (a.y + b.y) + (c.y + d.y);
        az += (a.z + b.z) + (c.z + d.z);
        aw += (a.w + b.w) + (c.w + d.w);
    }
    for (; j < s1; j++) {
        int i0 = g_csrsrc[j];
        float4 a = ((const float4*)(xin + (size_t)i0 * H))[lane];
        ax += a.x; ay += a.y; az += a.z; aw += a.w;
    }
    float inv = g_invdeg[w];
    float4 o = make_float4(ax * inv, ay * inv, az * inv, aw * inv);
    ((float4*)(g_agg + (size_t)w * H))[lane] = o;
}

// ---------------- fused GEMM + bias + LN + ReLU + residual ----------------
// out = relu(LN(agg@Wl^T + bl + x@Wr^T)) [+ x if layer>0]
// tile 128x128, 256 threads, 8x8 microtile; thread cols strided by 16.
extern __shared__ float smf[];

__global__ void __launch_bounds__(256, 1) k_gemm_ln(
    const float* __restrict__ Wl_all, const float* __restrict__ Wr_all,
    const float* __restrict__ bl_all, const float* __restrict__ gamma_all,
    const float* __restrict__ beta_all, int layer)
{
    const int SWP = 129;
    float* sA = smf;                 // 2 * 128*128 floats
    float* sW = smf + 2 * H * H;     // 32 * 129 floats
    const float* __restrict__ xin = g_X[layer];
    float* __restrict__ xout = g_X[layer + 1];
    const float* bl    = bl_all    + layer * H;
    const float* gamma = gamma_all + layer * H;
    const float* beta  = beta_all  + layer * H;

    int tid = threadIdx.x;
    int tr = tid >> 4, tc = tid & 15;
    size_t rowBase = (size_t)blockIdx.x * 128;

    // load A tiles (agg, x)
    {
        const float4* g0 = (const float4*)(g_agg + rowBase * H);
        const float4* g1 = (const float4*)(xin + rowBase * H);
        float4* s0 = (float4*)sA;
        float4* s1 = (float4*)(sA + H * H);
        #pragma unroll
        for (int it = 0; it < 16; it++) {
            s0[tid + it * 256] = g0[tid + it * 256];
            s1[tid + it * 256] = g1[tid + it * 256];
        }
    }

    float acc[8][8];
    #pragma unroll
    for (int i = 0; i < 8; i++)
        #pragma unroll
        for (int j = 0; j < 8; j++) acc[i][j] = 0.f;

    for (int m = 0; m < 2; m++) {
        const float* __restrict__ W = (m == 0) ? (Wl_all + layer * H * H)
                                               : (Wr_all + layer * H * H);
        const float* sAm = sA + m * H * H;
        for (int kc = 0; kc < 4; kc++) {
            __syncthreads();
            {   // transpose-load W chunk: sW[kk][o] = W[o*H + kc*32 + kk]
                int kk = tid & 31, ob = tid >> 5;
                #pragma unroll
                for (int it = 0; it < 16; it++) {
                    int o = ob + it * 8;
                    sW[kk * SWP + o] = W[o * H + kc * 32 + kk];
                }
            }
            __syncthreads();
            #pragma unroll 8
            for (int kk = 0; kk < 32; kk++) {
                int k = kc * 32 + kk;
                float a[8], w[8];
                #pragma unroll
                for (int i = 0; i < 8; i++) a[i] = sAm[(tr * 8 + i) * H + k];
                #pragma unroll
                for (int j = 0; j < 8; j++) w[j] = sW[kk * SWP + tc + j * 16];
                #pragma unroll
                for (int i = 0; i < 8; i++)
                    #pragma unroll
                    for (int j = 0; j < 8; j++)
                        acc[i][j] = fmaf(a[i], w[j], acc[i][j]);
            }
        }
    }
    __syncthreads();

    // bias + stage C in smem (reuse sA)
    float* sC = sA;
    #pragma unroll
    for (int j = 0; j < 8; j++) {
        float bj = bl[tc + j * 16];
        #pragma unroll
        for (int i = 0; i < 8; i++)
            sC[(tr * 8 + i) * H + tc + j * 16] = acc[i][j] + bj;
    }
    __syncthreads();

    // LayerNorm + ReLU + residual, row-wise (warp per row-group)
    int wid = tid >> 5, lane = tid & 31;
    float4 g4 = ((const float4*)gamma)[lane];
    float4 b4 = ((const float4*)beta)[lane];
    for (int rr = 0; rr < 16; rr++) {
        int r = wid * 16 + rr;
        float4 v = ((float4*)(sC + r * H))[lane];
        float s = v.x + v.y + v.z + v.w;
        float q = v.x * v.x + v.y * v.y + v.z * v.z + v.w * v.w;
        #pragma unroll
        for (int off = 16; off; off >>= 1) {
            s += __shfl_xor_sync(0xffffffffu, s, off);
            q += __shfl_xor_sync(0xffffffffu, q, off);
        }
        float mu = s * (1.0f / H);
        float var = q * (1.0f / H) - mu * mu;
        float rs = rsqrtf(var + 1e-5f);
        float4 o;
        o.x = fmaxf((v.x - mu) * rs * g4.x + b4.x, 0.f);
        o.y = fmaxf((v.y - mu) * rs * g4.y + b4.y, 0.f);
        o.z = fmaxf((v.z - mu) * rs * g4.z + b4.z, 0.f);
        o.w = fmaxf((v.w - mu) * rs * g4.w + b4.w, 0.f);
        if (layer > 0) {
            float4 xi = ((const float4*)(xin + (rowBase + r) * H))[lane];
            o.x += xi.x; o.y += xi.y; o.z += xi.z; o.w += xi.w;
        }
        ((float4*)(xout + (rowBase + r) * H))[lane] = o;
    }
}

// ---------------- JK: out = concat(X0..X3) @ jkW^T + jkb ----------------
__global__ void __launch_bounds__(256) k_jk(
    const float* __restrict__ jkW, const float* __restrict__ jkb,
    float* __restrict__ out)
{
    const int SWP = 129;
    float* sA = smf;            // 128*128
    float* sW = smf + H * H;    // 32*129
    int tid = threadIdx.x;
    int tr = tid >> 4, tc = tid & 15;
    size_t rowBase = (size_t)blockIdx.x * 128;

    float acc[8][8];
    #pragma unroll
    for (int i = 0; i < 8; i++)
        #pragma unroll
        for (int j = 0; j < 8; j++) acc[i][j] = 0.f;

    for (int sidx = 0; sidx < 4; sidx++) {
        __syncthreads();
        {
            const float4* g = (const float4*)(g_X[sidx] + rowBase * H);
            float4* s4 = (float4*)sA;
            #pragma unroll
            for (int it = 0; it < 16; it++) s4[tid + it * 256] = g[tid + it * 256];
        }
        for (int kc = 0; kc < 4; kc++) {
            __syncthreads();
            {
                int kk = tid & 31, ob = tid >> 5;
                #pragma unroll
                for (int it = 0; it < 16; it++) {
                    int o = ob + it * 8;
                    sW[kk * SWP + o] = jkW[o * 512 + sidx * H + kc * 32 + kk];
                }
            }
            __syncthreads();
            #pragma unroll 8
            for (int kk = 0; kk < 32; kk++) {
                int k = kc * 32 + kk;
                float a[8], w[8];
                #pragma unroll
                for (int i = 0; i < 8; i++) a[i] = sA[(tr * 8 + i) * H + k];
                #pragma unroll
                for (int j = 0; j < 8; j++) w[j] = sW[kk * SWP + tc + j * 16];
                #pragma unroll
                for (int i = 0; i < 8; i++)
                    #pragma unroll
                    for (int j = 0; j < 8; j++)
                        acc[i][j] = fmaf(a[i], w[j], acc[i][j]);
            }
        }
    }

    #pragma unroll
    for (int j = 0; j < 8; j++) {
        float bj = jkb[tc + j * 16];
        #pragma unroll
        for (int i = 0; i < 8; i++) {
            size_t grow = rowBase + tr * 8 + i;
            if (grow < (size_t)NNODES)
                out[grow * H + tc + j * 16] = acc[i][j] + bj;
        }
    }
}

// ---------------- launch ----------------
extern "C" void kernel_launch(void* const* d_in, const int* in_sizes, int n_in,
                              void* d_out, int out_size) {
    const float* emb  = (const float*)d_in[0];
    const float* Wl   = (const float*)d_in[1];
    const float* bl   = (const float*)d_in[2];
    const float* Wr   = (const float*)d_in[3];
    const float* lg   = (const float*)d_in[4];
    const float* lb   = (const float*)d_in[5];
    const float* jkW  = (const float*)d_in[6];
    const float* jkb  = (const float*)d_in[7];
    const int*   ei   = (const int*)d_in[8];
    int E = in_sizes[8] / 2;
    const int* src = ei;
    const int* dst = ei + E;
    float* out = (float*)d_out;

    const int GEMM_SMEM = (2 * H * H + 32 * 129) * 4;   // 147584
    const int JK_SMEM   = (H * H + 32 * 129) * 4;       // 82048
    cudaFuncSetAttribute(k_gemm_ln, cudaFuncAttributeMaxDynamicSharedMemorySize, GEMM_SMEM);
    cudaFuncSetAttribute(k_jk,      cudaFuncAttributeMaxDynamicSharedMemorySize, JK_SMEM);

    k_zero_deg<<<(NP + 255) / 256, 256>>>();
    k_hist<<<(E + 255) / 256, 256>>>(dst, E);
    k_scan<<<1, 1024>>>();
    k_fill<<<(E + 255) / 256, 256>>>(src, dst, E);
    k_copy_emb<<<NP * (H / 4) / 256, 256>>>((const float4*)emb);

    for (int l = 0; l < 3; l++) {
        k_agg<<<NP / 8, 256>>>(l);
        k_gemm_ln<<<NP / H, 256, GEMM_SMEM>>>(Wl, Wr, bl, lg, lb, l);
    }
    k_jk<<<NP / H, 256, JK_SMEM>>>(jkW, jkb, out);
}

// round 3
// speedup vs baseline: 1.3430x; 1.3430x over previous
#include <cuda_runtime.h>
#include <cuda_bf16.h>
#include <cstdint>

#define NNODES 100000
#define NP     100352            // multiple of 1024 and 128
#define H      128
#define EMAX   1600000

// ---------------- device scratch ----------------
__device__ float g_X[4][(size_t)NP * H];
__device__ float g_agg[(size_t)NP * H];
__device__ int   g_deg[NP];
__device__ float g_invdeg[NP];
__device__ int   g_rowstart[NP + 1];
__device__ int   g_cursor[NP];
__device__ int   g_csrsrc[EMAX];
// fragment-ordered operands
__device__ uint8_t g_afrag[(size_t)NP * 2048];        // up to KS=32: NP/16 * 32 * 32 lanes * 32B
__device__ uint8_t g_wfrag[5 * 131072];               // 3 layers + 2 JK phases

// ---------------- CSR build ----------------
__global__ void k_zero_deg() {
    int i = blockIdx.x * blockDim.x + threadIdx.x;
    if (i < NP) g_deg[i] = 0;
}
__global__ void k_hist(const int* __restrict__ dst, int E) {
    int i = blockIdx.x * blockDim.x + threadIdx.x;
    if (i < E) atomicAdd(&g_deg[dst[i]], 1);
}
__global__ void k_scan() {
    __shared__ int warp_tot[32];
    int t = threadIdx.x, lane = t & 31, wid = t >> 5;
    int running = 0;
    for (int base = 0; base < NP; base += 1024) {
        int v = g_deg[base + t];
        int x = v;
        #pragma unroll
        for (int d = 1; d < 32; d <<= 1) {
            int y = __shfl_up_sync(0xffffffffu, x, d);
            if (lane >= d) x += y;
        }
        if (lane == 31) warp_tot[wid] = x;
        __syncthreads();
        if (wid == 0) {
            int y = warp_tot[lane];
            #pragma unroll
            for (int d = 1; d < 32; d <<= 1) {
                int z = __shfl_up_sync(0xffffffffu, y, d);
                if (lane >= d) y += z;
            }
            warp_tot[lane] = y;
        }
        __syncthreads();
        int warp_off = (wid == 0) ? 0 : warp_tot[wid - 1];
        g_rowstart[base + t] = running + warp_off + x - v;
        int block_tot = warp_tot[31];
        __syncthreads();
        running += block_tot;
        g_invdeg[base + t] = 1.0f / fmaxf((float)v, 1.0f);
        g_cursor[base + t] = 0;
    }
    if (t == 0) g_rowstart[NP] = running;
}
__global__ void k_fill(const int* __restrict__ src, const int* __restrict__ dst, int E) {
    int i = blockIdx.x * blockDim.x + threadIdx.x;
    if (i < E) {
        int d = dst[i];
        int p = atomicAdd(&g_cursor[d], 1);
        g_csrsrc[g_rowstart[d] + p] = src[i];
    }
}
__global__ void k_copy_emb(const float4* __restrict__ emb) {
    int i = blockIdx.x * blockDim.x + threadIdx.x;
    float4 v = make_float4(0.f, 0.f, 0.f, 0.f);
    if (i < NNODES * (H / 4)) v = emb[i];
    ((float4*)g_X[0])[i] = v;
}

// ---------------- aggregation ----------------
__global__ void k_agg(int layer) {
    int w = (blockIdx.x * blockDim.x + threadIdx.x) >> 5;
    if (w >= NP) return;
    int lane = threadIdx.x & 31;
    const float* __restrict__ xin = g_X[layer];
    int s0 = g_rowstart[w], s1 = g_rowstart[w + 1];
    float ax = 0.f, ay = 0.f, az = 0.f, aw = 0.f;
    int j = s0;
    for (; j + 4 <= s1; j += 4) {
        int i0 = g_csrsrc[j], i1 = g_csrsrc[j + 1], i2 = g_csrsrc[j + 2], i3 = g_csrsrc[j + 3];
        float4 a = ((const float4*)(xin + (size_t)i0 * H))[lane];
        float4 b = ((const float4*)(xin + (size_t)i1 * H))[lane];
        float4 c = ((const float4*)(xin + (size_t)i2 * H))[lane];
        float4 d = ((const float4*)(xin + (size_t)i3 * H))[lane];
        ax += (a.x + b.x) + (c.x + d.x);
        ay += (a.y + b.y) + (c.y + d.y);
        az += (a.z + b.z) + (c.z + d.z);
        aw += (a.w + b.w) + (c.w + d.w);
    }
    for (; j < s1; j++) {
        int i0 = g_csrsrc[j];
        float4 a = ((const float4*)(xin + (size_t)i0 * H))[lane];
        ax += a.x; ay += a.y; az += a.z; aw += a.w;
    }
    float inv = g_invdeg[w];
    float4 o = make_float4(ax * inv, ay * inv, az * inv, aw * inv);
    ((float4*)(g_agg + (size_t)w * H))[lane] = o;
}

// ---------------- bf16 hi/lo split ----------------
__device__ __forceinline__ void split2(float v0, float v1, uint32_t& ph, uint32_t& pl) {
    __nv_bfloat16 h0 = __float2bfloat16(v0), h1 = __float2bfloat16(v1);
    float r0 = v0 - __bfloat162float(h0), r1 = v1 - __bfloat162float(h1);
    __nv_bfloat16 l0 = __float2bfloat16(r0), l1 = __float2bfloat16(r1);
    ph = ((uint32_t)__bfloat16_as_ushort(h1) << 16) | (uint32_t)__bfloat16_as_ushort(h0);
    pl = ((uint32_t)__bfloat16_as_ushort(l1) << 16) | (uint32_t)__bfloat16_as_ushort(l0);
}

// ---------------- W fragment build ----------------
// target t: 0..2 = layer (k<128: Wl, k>=128: Wr), 3..4 = jk phase (jkW cols h*256 + k)
// layout per target: [(nt*16+ks)*32 + lane] * 16B = {bhi0, bhi1, blo0, blo1}
// fragment mapping: n = nt*8 + (lane>>2); k = ks*16 + (lane&3)*2; b0 = W[n][k..k+1], b1 = W[n][k+8..k+9]
__global__ void k_conv_w(const float* __restrict__ Wl, const float* __restrict__ Wr,
                         const float* __restrict__ jkW) {
    int idx = blockIdx.x * blockDim.x + threadIdx.x;
    if (idx >= 5 * 16 * 16 * 32) return;
    int lane = idx & 31;
    int ks = (idx >> 5) & 15;
    int nt = (idx >> 9) & 15;
    int tgt = idx >> 13;
    int g = lane >> 2, tg = lane & 3;
    int n = nt * 8 + g;
    int k = ks * 16 + tg * 2;

    float v[4];
    if (tgt < 3) {
        #pragma unroll
        for (int q = 0; q < 4; q++) {
            int kk = k + (q >> 1) * 8 + (q & 1);
            v[q] = (kk < 128) ? Wl[(size_t)tgt * 16384 + n * 128 + kk]
                              : Wr[(size_t)tgt * 16384 + n * 128 + kk - 128];
        }
    } else {
        int h = tgt - 3;
        #pragma unroll
        for (int q = 0; q < 4; q++) {
            int kk = k + (q >> 1) * 8 + (q & 1);
            v[q] = jkW[(size_t)n * 512 + h * 256 + kk];
        }
    }
    uint32_t bh0, bl0, bh1, bl1;
    split2(v[0], v[1], bh0, bl0);
    split2(v[2], v[3], bh1, bl1);
    uint4 o = make_uint4(bh0, bh1, bl0, bl1);
    *(uint4*)(g_wfrag + (size_t)tgt * 131072 + ((size_t)((nt * 16 + ks) * 32 + lane)) * 16) = o;
}

// ---------------- A fragment build ----------------
// mode 0..2: layer (k<128: agg, else X[mode]); mode 3: jk (X[k/128]); KS = 16 or 32
// layout: [(mt*KS + ks)*32 + lane]*32B = {ahi0..3, alo0..3}
// a0=(m0,k), a1=(m1,k), a2=(m0,k+8), a3=(m1,k+8); m0=mt*16+g, m1=m0+8; k=ks*16+tg*2 (pairs k,k+1)
__global__ void k_conv_a(int mode, int KS) {
    int idx = blockIdx.x * blockDim.x + threadIdx.x;
    if (idx >= (NP / 16) * KS * 32) return;
    int lane = idx & 31;
    int ks = (idx >> 5) % KS;
    int mt = idx / (32 * KS);
    int g = lane >> 2, tg = lane & 3;
    size_t m0 = (size_t)mt * 16 + g, m1 = m0 + 8;
    int K0 = ks * 16;

    const float* s;
    if (mode < 3) s = (K0 < 128) ? g_agg : g_X[mode];
    else          s = g_X[K0 >> 7];
    int kl = (K0 & 127) + tg * 2;

    float2 p00 = *(const float2*)(s + m0 * H + kl);
    float2 p10 = *(const float2*)(s + m1 * H + kl);
    float2 p01 = *(const float2*)(s + m0 * H + kl + 8);
    float2 p11 = *(const float2*)(s + m1 * H + kl + 8);

    uint32_t h0, l0, h1, l1, h2, l2, h3, l3;
    split2(p00.x, p00.y, h0, l0);
    split2(p10.x, p10.y, h1, l1);
    split2(p01.x, p01.y, h2, l2);
    split2(p11.x, p11.y, h3, l3);

    uint4* dst = (uint4*)(g_afrag + ((size_t)(mt * KS + ks) * 32 + lane) * 32);
    dst[0] = make_uint4(h0, h1, h2, h3);
    dst[1] = make_uint4(l0, l1, l2, l3);
}

// ---------------- mma helper ----------------
__device__ __forceinline__ void mma_bf16(float* c, uint4 a, uint32_t b0, uint32_t b1) {
    asm volatile(
        "mma.sync.aligned.m16n8k16.row.col.f32.bf16.bf16.f32 "
        "{%0,%1,%2,%3}, {%4,%5,%6,%7}, {%8,%9}, {%0,%1,%2,%3};"
        : "+f"(c[0]), "+f"(c[1]), "+f"(c[2]), "+f"(c[3])
        : "r"(a.x), "r"(a.y), "r"(a.z), "r"(a.w), "r"(b0), "r"(b1));
}

// ---------------- GEMM (+ fused bias/LN/ReLU/residual for layers) ----------------
// grid: NP/128 CTAs, 256 threads (8 warps); warp handles 16 rows x 128 cols.
// do_ln=1: layer mode; do_ln=0: JK (bias only, write to outp, guard NNODES).
__global__ void __launch_bounds__(256, 1) k_mma(
    int KS, int wtgt0, int nphase, int do_ln, int layer,
    const float* __restrict__ bias, const float* __restrict__ gamma,
    const float* __restrict__ beta, float* __restrict__ outp)
{
    extern __shared__ uint8_t smem[];
    float* s_bias  = (float*)(smem + 131072);
    float* s_gamma = s_bias + 128;
    float* s_beta  = s_gamma + 128;
    int tid = threadIdx.x, wid = tid >> 5, lane = tid & 31;
    int g = lane >> 2, tg = lane & 3;
    int mt = blockIdx.x * 8 + wid;

    if (tid < 128) {
        s_bias[tid] = bias[tid];
        if (do_ln) { s_gamma[tid] = gamma[tid]; s_beta[tid] = beta[tid]; }
    }

    float acc[16][4];
    #pragma unroll
    for (int nt = 0; nt < 16; nt++)
        #pragma unroll
        for (int q = 0; q < 4; q++) acc[nt][q] = 0.f;

    for (int ph = 0; ph < nphase; ph++) {
        __syncthreads();
        {   // copy W fragment blob to smem (128KB)
            const uint4* wsrc = (const uint4*)(g_wfrag + (size_t)(wtgt0 + ph) * 131072);
            uint4* wdst = (uint4*)smem;
            #pragma unroll
            for (int i = 0; i < 32; i++) wdst[tid + i * 256] = wsrc[tid + i * 256];
        }
        __syncthreads();
        for (int ksl = 0; ksl < 16; ksl++) {
            int gks = ph * 16 + ksl;
            const uint4* ap = (const uint4*)(g_afrag + ((size_t)(mt * KS + gks) * 32 + lane) * 32);
            uint4 ah = ap[0], al = ap[1];
            #pragma unroll
            for (int nt = 0; nt < 16; nt++) {
                uint4 b = ((const uint4*)smem)[(nt * 16 + ksl) * 32 + lane];
                mma_bf16(acc[nt], ah, b.x, b.y);   // ah * wh
                mma_bf16(acc[nt], ah, b.z, b.w);   // ah * wl
                mma_bf16(acc[nt], al, b.x, b.y);   // al * wh
            }
        }
    }

    // ---- epilogue ----
    size_t m0 = (size_t)mt * 16 + g, m1 = m0 + 8;

    // bias
    #pragma unroll
    for (int nt = 0; nt < 16; nt++) {
        int n0 = nt * 8 + tg * 2;
        float b0 = s_bias[n0], b1 = s_bias[n0 + 1];
        acc[nt][0] += b0; acc[nt][1] += b1;
        acc[nt][2] += b0; acc[nt][3] += b1;
    }

    if (do_ln) {
        float s0 = 0.f, q0 = 0.f, s1 = 0.f, q1 = 0.f;
        #pragma unroll
        for (int nt = 0; nt < 16; nt++) {
            s0 += acc[nt][0] + acc[nt][1];
            q0 += acc[nt][0] * acc[nt][0] + acc[nt][1] * acc[nt][1];
            s1 += acc[nt][2] + acc[nt][3];
            q1 += acc[nt][2] * acc[nt][2] + acc[nt][3] * acc[nt][3];
        }
        #pragma unroll
        for (int o = 1; o <= 2; o <<= 1) {
            s0 += __shfl_xor_sync(0xffffffffu, s0, o);
            q0 += __shfl_xor_sync(0xffffffffu, q0, o);
            s1 += __shfl_xor_sync(0xffffffffu, s1, o);
            q1 += __shfl_xor_sync(0xffffffffu, q1, o);
        }
        float mu0 = s0 * (1.0f / H), mu1 = s1 * (1.0f / H);
        float rs0 = rsqrtf(q0 * (1.0f / H) - mu0 * mu0 + 1e-5f);
        float rs1 = rsqrtf(q1 * (1.0f / H) - mu1 * mu1 + 1e-5f);

        const float* xin = g_X[layer];
        float* xout = g_X[layer + 1];
        #pragma unroll
        for (int nt = 0; nt < 16; nt++) {
            int n0 = nt * 8 + tg * 2;
            float ga0 = s_gamma[n0], ga1 = s_gamma[n0 + 1];
            float be0 = s_beta[n0],  be1 = s_beta[n0 + 1];
            float2 o0, o1;
            o0.x = fmaxf((acc[nt][0] - mu0) * rs0 * ga0 + be0, 0.f);
            o0.y = fmaxf((acc[nt][1] - mu0) * rs0 * ga1 + be1, 0.f);
            o1.x = fmaxf((acc[nt][2] - mu1) * rs1 * ga0 + be0, 0.f);
            o1.y = fmaxf((acc[nt][3] - mu1) * rs1 * ga1 + be1, 0.f);
            if (layer > 0) {
                float2 r0 = *(const float2*)(xin + m0 * H + n0);
                float2 r1 = *(const float2*)(xin + m1 * H + n0);
                o0.x += r0.x; o0.y += r0.y;
                o1.x += r1.x; o1.y += r1.y;
            }
            *(float2*)(xout + m0 * H + n0) = o0;
            *(float2*)(xout + m1 * H + n0) = o1;
        }
    } else {
        bool w0 = m0 < (size_t)NNODES, w1 = m1 < (size_t)NNODES;
        #pragma unroll
        for (int nt = 0; nt < 16; nt++) {
            int n0 = nt * 8 + tg * 2;
            if (w0) *(float2*)(outp + m0 * H + n0) = make_float2(acc[nt][0], acc[nt][1]);
            if (w1) *(float2*)(outp + m1 * H + n0) = make_float2(acc[nt][2], acc[nt][3]);
        }
    }
}

// ---------------- launch ----------------
extern "C" void kernel_launch(void* const* d_in, const int* in_sizes, int n_in,
                              void* d_out, int out_size) {
    const float* emb = (const float*)d_in[0];
    const float* Wl  = (const float*)d_in[1];
    const float* bl  = (const float*)d_in[2];
    const float* Wr  = (const float*)d_in[3];
    const float* lg  = (const float*)d_in[4];
    const float* lb  = (const float*)d_in[5];
    const float* jkW = (const float*)d_in[6];
    const float* jkb = (const float*)d_in[7];
    const int*   ei  = (const int*)d_in[8];
    int E = in_sizes[8] / 2;
    const int* src = ei;
    const int* dst = ei + E;
    float* out = (float*)d_out;

    const int MMA_SMEM = 131072 + 3 * 128 * 4;   // W frags + bias/gamma/beta
    cudaFuncSetAttribute(k_mma, cudaFuncAttributeMaxDynamicSharedMemorySize, MMA_SMEM);

    k_zero_deg<<<(NP + 255) / 256, 256>>>();
    k_hist<<<(E + 255) / 256, 256>>>(dst, E);
    k_scan<<<1, 1024>>>();
    k_fill<<<(E + 255) / 256, 256>>>(src, dst, E);
    k_copy_emb<<<NP * (H / 4) / 256, 256>>>((const float4*)emb);
    k_conv_w<<<(5 * 16 * 16 * 32 + 255) / 256, 256>>>(Wl, Wr, jkW);

    for (int l = 0; l < 3; l++) {
        k_agg<<<NP / 8, 256>>>(l);
        k_conv_a<<<((NP / 16) * 16 * 32 + 255) / 256, 256>>>(l, 16);
        k_mma<<<NP / 128, 256, MMA_SMEM>>>(16, l, 1, 1, l,
                                           bl + l * H, lg + l * H, lb + l * H, nullptr);
    }
    k_conv_a<<<((NP / 16) * 32 * 32 + 255) / 256, 256>>>(3, 32);
    k_mma<<<NP / 128, 256, MMA_SMEM>>>(32, 3, 2, 0, 0, jkb, nullptr, nullptr, out);
}